// round 16
// baseline (speedup 1.0000x reference)
#include <cuda_runtime.h>
#include <cuda_bf16.h>
#include <stdint.h>

#define N_NODES 50000
#define N_EDGES 300000
#define DIM 256
#define ALPHA 0.1f

#define SCAN_B 1024
#define N_SCAN_BLK ((N_NODES + SCAN_B - 1) / SCAN_B)   // 49

// ---------------------------------------------------------------------------
// __device__ scratch (allocation-free rule)
// ---------------------------------------------------------------------------
__device__ float g_bufA[(size_t)N_NODES * DIM];
__device__ float g_bufB[(size_t)N_NODES * DIM];
__device__ __nv_bfloat16 g_ahi[(size_t)N_NODES * DIM];   // split-hi of h
__device__ __nv_bfloat16 g_alo[(size_t)N_NODES * DIM];   // split-lo of h
__device__ __nv_bfloat16 g_whi[DIM * DIM];               // W^T hi  [n][k]
__device__ __nv_bfloat16 g_wlo[DIM * DIM];               // W^T lo  [n][k]
__device__ float g_rnorm[N_NODES];
__device__ int   g_src[N_EDGES];
__device__ int   g_dst[N_EDGES];
__device__ int   g_csrc[N_EDGES];
__device__ int   g_rowptr[N_NODES + 1];
__device__ int   g_ideg[N_NODES];
__device__ int   g_cursor[N_NODES];
__device__ int   g_bsum[N_SCAN_BLK];
__device__ int   g_is64;

// ---------------------------------------------------------------------------
// Base-ISA helpers (sm_80+; safe for .target sm_103)
// ---------------------------------------------------------------------------
__device__ __forceinline__ uint32_t smem_u32(const void* p) {
    uint32_t a;
    asm("{ .reg .u64 t; cvta.to.shared.u64 t, %1; cvt.u32.u64 %0, t; }"
        : "=r"(a) : "l"(p));
    return a;
}

__device__ __forceinline__ void ldsm4(uint32_t* r, uint32_t a) {
    asm volatile("ldmatrix.sync.aligned.m8n8.x4.shared.b16 {%0,%1,%2,%3}, [%4];"
        : "=r"(r[0]), "=r"(r[1]), "=r"(r[2]), "=r"(r[3]) : "r"(a));
}

__device__ __forceinline__ void mma16816(float* c, const uint32_t* a,
                                         uint32_t b0, uint32_t b1) {
    asm volatile(
        "mma.sync.aligned.m16n8k16.row.col.f32.bf16.bf16.f32 "
        "{%0,%1,%2,%3}, {%4,%5,%6,%7}, {%8,%9}, {%0,%1,%2,%3};"
        : "+f"(c[0]), "+f"(c[1]), "+f"(c[2]), "+f"(c[3])
        : "r"(a[0]), "r"(a[1]), "r"(a[2]), "r"(a[3]), "r"(b0), "r"(b1));
}

__device__ __forceinline__ void cp16(uint32_t dst, const void* src, int srcsz) {
    asm volatile("cp.async.cg.shared.global [%0], [%1], 16, %2;"
        :: "r"(dst), "l"(src), "r"(srcsz) : "memory");
}
#define CP_COMMIT() asm volatile("cp.async.commit_group;" ::: "memory")
#define CP_WAIT0()  asm volatile("cp.async.wait_group 0;" ::: "memory")

#define SWZOFF(row, c) ((unsigned)((row) * 128 + (((c) ^ ((row) & 7)) << 4)))

// ---------------------------------------------------------------------------
// Edge dtype detect + decode (int64 vs int32 robust), clamped.
// hist fused into decode (ideg zeroed beforehand).
// ---------------------------------------------------------------------------
__global__ void detect_kernel(const int* __restrict__ buf32) {
    if (threadIdx.x == 0 && blockIdx.x == 0) {
        int is64 = 1;
        for (int i = 0; i < 512; i++)
            if (buf32[2 * i + 1] != 0) { is64 = 0; break; }
        g_is64 = is64;
    }
}

__global__ void decode_hist_kernel(const void* __restrict__ buf) {
    int e = blockIdx.x * blockDim.x + threadIdx.x;
    if (e >= N_EDGES) return;
    int s, d;
    if (g_is64) {
        const long long* b = (const long long*)buf;
        s = (int)b[e];  d = (int)b[N_EDGES + e];
    } else {
        const int* b = (const int*)buf;
        s = b[e];       d = b[N_EDGES + e];
    }
    if (s < 0) s = 0; if (s >= N_NODES) s = N_NODES - 1;
    if (d < 0) d = 0; if (d >= N_NODES) d = N_NODES - 1;
    g_src[e] = s;
    g_dst[e] = d;
    atomicAdd(&g_ideg[d], 1);
}

// ---------------------------------------------------------------------------
// CSR build
// ---------------------------------------------------------------------------
__global__ void scan1_kernel() {
    __shared__ int s[SCAN_B];
    int tid = threadIdx.x;
    int i = blockIdx.x * SCAN_B + tid;
    int v = (i < N_NODES) ? g_ideg[i] : 0;
    s[tid] = v;
    __syncthreads();
    for (int off = 1; off < SCAN_B; off <<= 1) {
        int t = (tid >= off) ? s[tid - off] : 0;
        __syncthreads();
        s[tid] += t;
        __syncthreads();
    }
    if (i < N_NODES) g_rowptr[i] = s[tid] - v;
    if (tid == SCAN_B - 1) g_bsum[blockIdx.x] = s[tid];
}

__global__ void scan2_kernel() {
    __shared__ int s[N_SCAN_BLK];
    int tid = threadIdx.x;
    if (tid < N_SCAN_BLK) s[tid] = g_bsum[tid];
    __syncthreads();
    if (tid == 0) {
        int acc = 0;
        for (int i = 0; i < N_SCAN_BLK; i++) { int t = s[i]; s[i] = acc; acc += t; }
    }
    __syncthreads();
    if (tid < N_SCAN_BLK) g_bsum[tid] = s[tid];
}

// scan3 + rnorm fused
__global__ void scan3_kernel() {
    int i = blockIdx.x * SCAN_B + threadIdx.x;
    if (i < N_NODES) {
        g_rowptr[i] += g_bsum[blockIdx.x];
        g_rnorm[i] = (1.0f - ALPHA) / fmaxf((float)g_ideg[i], 1.0f);
    }
    if (i == 0) g_rowptr[N_NODES] = N_EDGES;
}

__global__ void fill_kernel() {
    int e = blockIdx.x * blockDim.x + threadIdx.x;
    if (e >= N_EDGES) return;
    int d = g_dst[e];
    int p = atomicAdd(&g_cursor[d], 1);
    g_csrc[g_rowptr[d] + p] = g_src[e];
}

// ---------------------------------------------------------------------------
// W split + transpose: g_whi/g_wlo[n][k] = bf16 hi/lo of W[k][n]
// ---------------------------------------------------------------------------
__global__ void wsplit_kernel(const float* __restrict__ W) {
    int idx = blockIdx.x * blockDim.x + threadIdx.x;
    if (idx >= DIM * DIM) return;
    int k = idx >> 8, n = idx & 255;
    float w = W[k * DIM + n];
    __nv_bfloat16 hi = __float2bfloat16_rn(w);
    float rem = w - __bfloat162float(hi);
    g_whi[n * DIM + k] = hi;
    g_wlo[n * DIM + k] = __float2bfloat16_rn(rem);
}

// ---------------------------------------------------------------------------
// Gather + mix, emitting bf16 split (hi/lo) GEMM operand rows.
// One warp per row; full grid occupancy.               [R9-proven, verbatim]
// ---------------------------------------------------------------------------
__global__ void gather_kernel(const float* __restrict__ x,
                              const float* __restrict__ x0) {
    int gw = (blockIdx.x * blockDim.x + threadIdx.x) >> 5;
    int lane = threadIdx.x & 31;
    if (gw >= N_NODES) return;
    int s = g_rowptr[gw], e = g_rowptr[gw + 1];
    float4 a0 = {0.f, 0.f, 0.f, 0.f}, a1 = {0.f, 0.f, 0.f, 0.f};
    for (int i = s; i < e; i++) {
        const float4* p = (const float4*)(x + (size_t)g_csrc[i] * DIM);
        float4 v0 = p[lane];
        float4 v1 = p[lane + 32];
        a0.x += v0.x; a0.y += v0.y; a0.z += v0.z; a0.w += v0.w;
        a1.x += v1.x; a1.y += v1.y; a1.z += v1.z; a1.w += v1.w;
    }
    float rn = g_rnorm[gw];
    const float4* q = (const float4*)(x0 + (size_t)gw * DIM);
    float4 q0 = q[lane], q1 = q[lane + 32];
    float h[8];
    h[0] = ALPHA * q0.x + rn * a0.x;  h[1] = ALPHA * q0.y + rn * a0.y;
    h[2] = ALPHA * q0.z + rn * a0.z;  h[3] = ALPHA * q0.w + rn * a0.w;
    h[4] = ALPHA * q1.x + rn * a1.x;  h[5] = ALPHA * q1.y + rn * a1.y;
    h[6] = ALPHA * q1.z + rn * a1.z;  h[7] = ALPHA * q1.w + rn * a1.w;

    __nv_bfloat162* oh = (__nv_bfloat162*)(g_ahi + (size_t)gw * DIM);
    __nv_bfloat162* ol = (__nv_bfloat162*)(g_alo + (size_t)gw * DIM);
    #pragma unroll
    for (int half = 0; half < 2; half++) {
        int base2 = (half == 0) ? lane * 2 : (lane + 32) * 2;
        #pragma unroll
        for (int p2 = 0; p2 < 2; p2++) {
            float f0 = h[half * 4 + p2 * 2 + 0];
            float f1 = h[half * 4 + p2 * 2 + 1];
            __nv_bfloat16 b0 = __float2bfloat16_rn(f0);
            __nv_bfloat16 b1 = __float2bfloat16_rn(f1);
            __nv_bfloat16 c0 = __float2bfloat16_rn(f0 - __bfloat162float(b0));
            __nv_bfloat16 c1 = __float2bfloat16_rn(f1 - __bfloat162float(b1));
            oh[base2 + p2] = __halves2bfloat162(b0, b1);
            ol[base2 + p2] = __halves2bfloat162(c0, c1);
        }
    }
}

// ---------------------------------------------------------------------------
// Pipelined warp-MMA bf16 split GEMM: out = relu(h @ W)
// R15 core with ONE change: term-major MMA ordering. Same-accumulator MMAs
// are now 16 instructions apart (was back-to-back), covering HMMA latency.
// Per-accumulator contribution order is unchanged -> bit-identical result.
// ---------------------------------------------------------------------------
#define STAGE_BYTES 65536

__device__ __forceinline__ void load_chunk(uint32_t ub, int m0, int n0, int k0,
                                           int tid) {
    #pragma unroll
    for (int t = 0; t < 4; t++) {
        int idx = tid + t * 256;
        int r = idx >> 3, j = idx & 7;
        int row = m0 + r;
        int sz = (row < N_NODES) ? 16 : 0;
        int rc = (row < N_NODES) ? row : (N_NODES - 1);
        unsigned off = SWZOFF(r, j);
        cp16(ub + off,          g_ahi + (size_t)rc * DIM + k0 + j * 8, sz);
        cp16(ub + 16384 + off,  g_alo + (size_t)rc * DIM + k0 + j * 8, sz);
    }
    #pragma unroll
    for (int t = 0; t < 4; t++) {
        int idx = tid + t * 256;
        int r = idx >> 3, j = idx & 7;
        unsigned off = SWZOFF(r, j);
        cp16(ub + 32768 + off, g_whi + (size_t)(n0 + r) * DIM + k0 + j * 8, 16);
        cp16(ub + 49152 + off, g_wlo + (size_t)(n0 + r) * DIM + k0 + j * 8, 16);
    }
}

__global__ void __launch_bounds__(256) gemm_kernel(float* __restrict__ out) {
    extern __shared__ __align__(16) char dsm[];

    const int tid = threadIdx.x;
    const int wid = tid >> 5, lane = tid & 31;
    const int m0 = blockIdx.x * 128;
    const int n0 = blockIdx.y * 128;
    const int wm = (wid >> 1) * 32;
    const int wn = (wid & 1) * 64;

    const uint32_t usm = smem_u32(dsm);

    float acc[2][8][4] = {};

    load_chunk(usm, m0, n0, 0, tid);
    CP_COMMIT();

    for (int ch = 0; ch < 4; ch++) {
        const uint32_t ub = usm + (ch & 1) * STAGE_BYTES;
        CP_WAIT0();
        __syncthreads();
        if (ch < 3) {
            load_chunk(usm + ((ch + 1) & 1) * STAGE_BYTES, m0, n0,
                       (ch + 1) * 64, tid);
            CP_COMMIT();
        }

        const uint32_t uAhi = ub, uAlo = ub + 16384;
        const uint32_t uBhi = ub + 32768, uBlo = ub + 49152;

        #pragma unroll
        for (int kk = 0; kk < 4; kk++) {
            uint32_t ah[2][4], al[2][4], bh[4][4], bl[4][4];
            #pragma unroll
            for (int mi = 0; mi < 2; mi++) {
                int row = wm + mi * 16 + (lane & 15);
                int c = kk * 2 + (lane >> 4);
                unsigned off = SWZOFF(row, c);
                ldsm4(ah[mi], uAhi + off);
                ldsm4(al[mi], uAlo + off);
            }
            #pragma unroll
            for (int q = 0; q < 4; q++) {
                int n = wn + q * 16 + ((lane >> 4) << 3) + (lane & 7);
                int c = kk * 2 + ((lane >> 3) & 1);
                unsigned off = SWZOFF(n, c);
                ldsm4(bh[q], uBhi + off);
                ldsm4(bl[q], uBlo + off);
            }
            // Term-major ordering: 16 independent MMAs between same-acc reuse.
            #pragma unroll
            for (int mi = 0; mi < 2; mi++)
                #pragma unroll
                for (int nj = 0; nj < 8; nj++) {
                    int q = nj >> 1, hb = (nj & 1) * 2;
                    mma16816(acc[mi][nj], ah[mi], bh[q][hb], bh[q][hb + 1]);
                }
            #pragma unroll
            for (int mi = 0; mi < 2; mi++)
                #pragma unroll
                for (int nj = 0; nj < 8; nj++) {
                    int q = nj >> 1, hb = (nj & 1) * 2;
                    mma16816(acc[mi][nj], ah[mi], bl[q][hb], bl[q][hb + 1]);
                }
            #pragma unroll
            for (int mi = 0; mi < 2; mi++)
                #pragma unroll
                for (int nj = 0; nj < 8; nj++) {
                    int q = nj >> 1, hb = (nj & 1) * 2;
                    mma16816(acc[mi][nj], al[mi], bh[q][hb], bh[q][hb + 1]);
                }
        }
        __syncthreads();
    }

    #pragma unroll
    for (int mi = 0; mi < 2; mi++) {
        #pragma unroll
        for (int nj = 0; nj < 8; nj++) {
            int r = m0 + wm + mi * 16 + (lane >> 2);
            int cbase = n0 + wn + nj * 8 + (lane & 3) * 2;
            float2 v0, v1;
            v0.x = fmaxf(acc[mi][nj][0], 0.f);
            v0.y = fmaxf(acc[mi][nj][1], 0.f);
            v1.x = fmaxf(acc[mi][nj][2], 0.f);
            v1.y = fmaxf(acc[mi][nj][3], 0.f);
            if (r < N_NODES)
                *(float2*)(out + (size_t)r * DIM + cbase) = v0;
            if (r + 8 < N_NODES)
                *(float2*)(out + (size_t)(r + 8) * DIM + cbase) = v1;
        }
    }
}

// ---------------------------------------------------------------------------
// Launch (all graph-capturable)
// ---------------------------------------------------------------------------
extern "C" void kernel_launch(void* const* d_in, const int* in_sizes, int n_in,
                              void* d_out, int out_size) {
    const float* x0   = (const float*)d_in[0];
    const void*  edge = d_in[1];
    const float* W    = (const float*)d_in[2];
    float*       out  = (float*)d_out;

    void *ideg_p, *cursor_p, *bufA_p, *bufB_p;
    cudaGetSymbolAddress(&ideg_p,   g_ideg);
    cudaGetSymbolAddress(&cursor_p, g_cursor);
    cudaGetSymbolAddress(&bufA_p,   g_bufA);
    cudaGetSymbolAddress(&bufB_p,   g_bufB);

    cudaFuncSetAttribute(gemm_kernel,
                         cudaFuncAttributeMaxDynamicSharedMemorySize,
                         2 * STAGE_BYTES);
    cudaFuncSetAttribute(gemm_kernel,
                         cudaFuncAttributePreferredSharedMemoryCarveout,
                         cudaSharedmemCarveoutMaxShared);

    const int EB = (N_EDGES + 255) / 256;

    // Prologue (layer-invariant)
    detect_kernel<<<1, 32>>>((const int*)edge);
    cudaMemsetAsync(ideg_p,   0, N_NODES * sizeof(int), 0);
    cudaMemsetAsync(cursor_p, 0, N_NODES * sizeof(int), 0);
    decode_hist_kernel<<<EB, 256>>>(edge);
    scan1_kernel<<<N_SCAN_BLK, SCAN_B>>>();
    scan2_kernel<<<1, 64>>>();
    scan3_kernel<<<N_SCAN_BLK, SCAN_B>>>();
    fill_kernel<<<EB, 256>>>();
    wsplit_kernel<<<(DIM * DIM + 255) / 256, 256>>>(W);

    float* layer_out[5] = {(float*)bufA_p, (float*)bufB_p,
                           (float*)bufA_p, (float*)bufB_p, out};

    dim3 ggrid((N_NODES + 127) / 128, DIM / 128);
    const int gather_blocks = (N_NODES * 32 + 255) / 256;

    const float* xin = x0;
    for (int l = 0; l < 5; l++) {
        gather_kernel<<<gather_blocks, 256>>>(xin, x0);
        gemm_kernel<<<ggrid, 256, 2 * STAGE_BYTES>>>(layer_out[l]);
        xin = layer_out[l];
    }
}

// round 17
// speedup vs baseline: 1.0527x; 1.0527x over previous
#include <cuda_runtime.h>
#include <cuda_bf16.h>
#include <stdint.h>

#define N_NODES 50000
#define N_EDGES 300000
#define DIM 256
#define ALPHA 0.1f

#define SCAN_B 1024
#define N_SCAN_BLK ((N_NODES + SCAN_B - 1) / SCAN_B)   // 49

#define H0 25088                      // 196 m-blocks * 128 rows
#define H1 (N_NODES - H0)             // 24912 -> 195 m-blocks

// ---------------------------------------------------------------------------
// __device__ scratch (allocation-free rule)
// ---------------------------------------------------------------------------
__device__ float g_bufA[(size_t)N_NODES * DIM];
__device__ float g_bufB[(size_t)N_NODES * DIM];
__device__ __nv_bfloat16 g_ahi[(size_t)N_NODES * DIM];   // split-hi of h
__device__ __nv_bfloat16 g_alo[(size_t)N_NODES * DIM];   // split-lo of h
__device__ __nv_bfloat16 g_whi[DIM * DIM];               // W^T hi  [n][k]
__device__ __nv_bfloat16 g_wlo[DIM * DIM];               // W^T lo  [n][k]
__device__ float g_rnorm[N_NODES];
__device__ int   g_src[N_EDGES];
__device__ int   g_dst[N_EDGES];
__device__ int   g_csrc[N_EDGES];
__device__ int   g_rowptr[N_NODES + 1];
__device__ int   g_ideg[N_NODES];
__device__ int   g_cursor[N_NODES];
__device__ int   g_bsum[N_SCAN_BLK];
__device__ int   g_is64;

// ---------------------------------------------------------------------------
// Base-ISA helpers (sm_80+; safe for .target sm_103)
// ---------------------------------------------------------------------------
__device__ __forceinline__ uint32_t smem_u32(const void* p) {
    uint32_t a;
    asm("{ .reg .u64 t; cvta.to.shared.u64 t, %1; cvt.u32.u64 %0, t; }"
        : "=r"(a) : "l"(p));
    return a;
}

__device__ __forceinline__ void ldsm4(uint32_t* r, uint32_t a) {
    asm volatile("ldmatrix.sync.aligned.m8n8.x4.shared.b16 {%0,%1,%2,%3}, [%4];"
        : "=r"(r[0]), "=r"(r[1]), "=r"(r[2]), "=r"(r[3]) : "r"(a));
}

__device__ __forceinline__ void mma16816(float* c, const uint32_t* a,
                                         uint32_t b0, uint32_t b1) {
    asm volatile(
        "mma.sync.aligned.m16n8k16.row.col.f32.bf16.bf16.f32 "
        "{%0,%1,%2,%3}, {%4,%5,%6,%7}, {%8,%9}, {%0,%1,%2,%3};"
        : "+f"(c[0]), "+f"(c[1]), "+f"(c[2]), "+f"(c[3])
        : "r"(a[0]), "r"(a[1]), "r"(a[2]), "r"(a[3]), "r"(b0), "r"(b1));
}

__device__ __forceinline__ void cp16(uint32_t dst, const void* src, int srcsz) {
    asm volatile("cp.async.cg.shared.global [%0], [%1], 16, %2;"
        :: "r"(dst), "l"(src), "r"(srcsz) : "memory");
}
#define CP_COMMIT() asm volatile("cp.async.commit_group;" ::: "memory")
#define CP_WAIT0()  asm volatile("cp.async.wait_group 0;" ::: "memory")

#define SWZOFF(row, c) ((unsigned)((row) * 128 + (((c) ^ ((row) & 7)) << 4)))

// ---------------------------------------------------------------------------
// Edge dtype detect + decode (int64 vs int32 robust), clamped.
// hist fused into decode (ideg zeroed beforehand).
// ---------------------------------------------------------------------------
__global__ void detect_kernel(const int* __restrict__ buf32) {
    if (threadIdx.x == 0 && blockIdx.x == 0) {
        int is64 = 1;
        for (int i = 0; i < 512; i++)
            if (buf32[2 * i + 1] != 0) { is64 = 0; break; }
        g_is64 = is64;
    }
}

__global__ void decode_hist_kernel(const void* __restrict__ buf) {
    int e = blockIdx.x * blockDim.x + threadIdx.x;
    if (e >= N_EDGES) return;
    int s, d;
    if (g_is64) {
        const long long* b = (const long long*)buf;
        s = (int)b[e];  d = (int)b[N_EDGES + e];
    } else {
        const int* b = (const int*)buf;
        s = b[e];       d = b[N_EDGES + e];
    }
    if (s < 0) s = 0; if (s >= N_NODES) s = N_NODES - 1;
    if (d < 0) d = 0; if (d >= N_NODES) d = N_NODES - 1;
    g_src[e] = s;
    g_dst[e] = d;
    atomicAdd(&g_ideg[d], 1);
}

// ---------------------------------------------------------------------------
// CSR build
// ---------------------------------------------------------------------------
__global__ void scan1_kernel() {
    __shared__ int s[SCAN_B];
    int tid = threadIdx.x;
    int i = blockIdx.x * SCAN_B + tid;
    int v = (i < N_NODES) ? g_ideg[i] : 0;
    s[tid] = v;
    __syncthreads();
    for (int off = 1; off < SCAN_B; off <<= 1) {
        int t = (tid >= off) ? s[tid - off] : 0;
        __syncthreads();
        s[tid] += t;
        __syncthreads();
    }
    if (i < N_NODES) g_rowptr[i] = s[tid] - v;
    if (tid == SCAN_B - 1) g_bsum[blockIdx.x] = s[tid];
}

__global__ void scan2_kernel() {
    __shared__ int s[N_SCAN_BLK];
    int tid = threadIdx.x;
    if (tid < N_SCAN_BLK) s[tid] = g_bsum[tid];
    __syncthreads();
    if (tid == 0) {
        int acc = 0;
        for (int i = 0; i < N_SCAN_BLK; i++) { int t = s[i]; s[i] = acc; acc += t; }
    }
    __syncthreads();
    if (tid < N_SCAN_BLK) g_bsum[tid] = s[tid];
}

// scan3 + rnorm fused
__global__ void scan3_kernel() {
    int i = blockIdx.x * SCAN_B + threadIdx.x;
    if (i < N_NODES) {
        g_rowptr[i] += g_bsum[blockIdx.x];
        g_rnorm[i] = (1.0f - ALPHA) / fmaxf((float)g_ideg[i], 1.0f);
    }
    if (i == 0) g_rowptr[N_NODES] = N_EDGES;
}

__global__ void fill_kernel() {
    int e = blockIdx.x * blockDim.x + threadIdx.x;
    if (e >= N_EDGES) return;
    int d = g_dst[e];
    int p = atomicAdd(&g_cursor[d], 1);
    g_csrc[g_rowptr[d] + p] = g_src[e];
}

// ---------------------------------------------------------------------------
// W split + transpose: g_whi/g_wlo[n][k] = bf16 hi/lo of W[k][n]
// ---------------------------------------------------------------------------
__global__ void wsplit_kernel(const float* __restrict__ W) {
    int idx = blockIdx.x * blockDim.x + threadIdx.x;
    if (idx >= DIM * DIM) return;
    int k = idx >> 8, n = idx & 255;
    float w = W[k * DIM + n];
    __nv_bfloat16 hi = __float2bfloat16_rn(w);
    float rem = w - __bfloat162float(hi);
    g_whi[n * DIM + k] = hi;
    g_wlo[n * DIM + k] = __float2bfloat16_rn(rem);
}

// ---------------------------------------------------------------------------
// Gather + mix, emitting bf16 split (hi/lo) GEMM operand rows.
// One warp per row in [base, base+count); full grid occupancy.
// ---------------------------------------------------------------------------
__global__ void gather_kernel(const float* __restrict__ x,
                              const float* __restrict__ x0,
                              int base, int count) {
    int gw = base + ((blockIdx.x * blockDim.x + threadIdx.x) >> 5);
    int lane = threadIdx.x & 31;
    if (gw >= base + count || gw >= N_NODES) return;
    int s = g_rowptr[gw], e = g_rowptr[gw + 1];
    float4 a0 = {0.f, 0.f, 0.f, 0.f}, a1 = {0.f, 0.f, 0.f, 0.f};
    for (int i = s; i < e; i++) {
        const float4* p = (const float4*)(x + (size_t)g_csrc[i] * DIM);
        float4 v0 = p[lane];
        float4 v1 = p[lane + 32];
        a0.x += v0.x; a0.y += v0.y; a0.z += v0.z; a0.w += v0.w;
        a1.x += v1.x; a1.y += v1.y; a1.z += v1.z; a1.w += v1.w;
    }
    float rn = g_rnorm[gw];
    const float4* q = (const float4*)(x0 + (size_t)gw * DIM);
    float4 q0 = q[lane], q1 = q[lane + 32];
    float h[8];
    h[0] = ALPHA * q0.x + rn * a0.x;  h[1] = ALPHA * q0.y + rn * a0.y;
    h[2] = ALPHA * q0.z + rn * a0.z;  h[3] = ALPHA * q0.w + rn * a0.w;
    h[4] = ALPHA * q1.x + rn * a1.x;  h[5] = ALPHA * q1.y + rn * a1.y;
    h[6] = ALPHA * q1.z + rn * a1.z;  h[7] = ALPHA * q1.w + rn * a1.w;

    __nv_bfloat162* oh = (__nv_bfloat162*)(g_ahi + (size_t)gw * DIM);
    __nv_bfloat162* ol = (__nv_bfloat162*)(g_alo + (size_t)gw * DIM);
    #pragma unroll
    for (int half = 0; half < 2; half++) {
        int base2 = (half == 0) ? lane * 2 : (lane + 32) * 2;
        #pragma unroll
        for (int p2 = 0; p2 < 2; p2++) {
            float f0 = h[half * 4 + p2 * 2 + 0];
            float f1 = h[half * 4 + p2 * 2 + 1];
            __nv_bfloat16 b0 = __float2bfloat16_rn(f0);
            __nv_bfloat16 b1 = __float2bfloat16_rn(f1);
            __nv_bfloat16 c0 = __float2bfloat16_rn(f0 - __bfloat162float(b0));
            __nv_bfloat16 c1 = __float2bfloat16_rn(f1 - __bfloat162float(b1));
            oh[base2 + p2] = __halves2bfloat162(b0, b1);
            ol[base2 + p2] = __halves2bfloat162(c0, c1);
        }
    }
}

// ---------------------------------------------------------------------------
// Pipelined warp-MMA bf16 split GEMM: out = relu(h @ W)   [R15-proven core]
// CTA tile 128x128 starting at m0base + bx*128.
// ---------------------------------------------------------------------------
#define STAGE_BYTES 65536

__device__ __forceinline__ void load_chunk(uint32_t ub, int m0, int n0, int k0,
                                           int tid) {
    #pragma unroll
    for (int t = 0; t < 4; t++) {
        int idx = tid + t * 256;
        int r = idx >> 3, j = idx & 7;
        int row = m0 + r;
        int sz = (row < N_NODES) ? 16 : 0;
        int rc = (row < N_NODES) ? row : (N_NODES - 1);
        unsigned off = SWZOFF(r, j);
        cp16(ub + off,          g_ahi + (size_t)rc * DIM + k0 + j * 8, sz);
        cp16(ub + 16384 + off,  g_alo + (size_t)rc * DIM + k0 + j * 8, sz);
    }
    #pragma unroll
    for (int t = 0; t < 4; t++) {
        int idx = tid + t * 256;
        int r = idx >> 3, j = idx & 7;
        unsigned off = SWZOFF(r, j);
        cp16(ub + 32768 + off, g_whi + (size_t)(n0 + r) * DIM + k0 + j * 8, 16);
        cp16(ub + 49152 + off, g_wlo + (size_t)(n0 + r) * DIM + k0 + j * 8, 16);
    }
}

__global__ void __launch_bounds__(256) gemm_kernel(float* __restrict__ out,
                                                   int m0base) {
    extern __shared__ __align__(16) char dsm[];

    const int tid = threadIdx.x;
    const int wid = tid >> 5, lane = tid & 31;
    const int m0 = m0base + blockIdx.x * 128;
    const int n0 = blockIdx.y * 128;
    const int wm = (wid >> 1) * 32;
    const int wn = (wid & 1) * 64;

    const uint32_t usm = smem_u32(dsm);

    float acc[2][8][4] = {};

    load_chunk(usm, m0, n0, 0, tid);
    CP_COMMIT();

    for (int ch = 0; ch < 4; ch++) {
        const uint32_t ub = usm + (ch & 1) * STAGE_BYTES;
        CP_WAIT0();
        __syncthreads();
        if (ch < 3) {
            load_chunk(usm + ((ch + 1) & 1) * STAGE_BYTES, m0, n0,
                       (ch + 1) * 64, tid);
            CP_COMMIT();
        }

        const uint32_t uAhi = ub, uAlo = ub + 16384;
        const uint32_t uBhi = ub + 32768, uBlo = ub + 49152;

        #pragma unroll
        for (int kk = 0; kk < 4; kk++) {
            uint32_t ah[2][4], al[2][4], bh[4][4], bl[4][4];
            #pragma unroll
            for (int mi = 0; mi < 2; mi++) {
                int row = wm + mi * 16 + (lane & 15);
                int c = kk * 2 + (lane >> 4);
                unsigned off = SWZOFF(row, c);
                ldsm4(ah[mi], uAhi + off);
                ldsm4(al[mi], uAlo + off);
            }
            #pragma unroll
            for (int q = 0; q < 4; q++) {
                int n = wn + q * 16 + ((lane >> 4) << 3) + (lane & 7);
                int c = kk * 2 + ((lane >> 3) & 1);
                unsigned off = SWZOFF(n, c);
                ldsm4(bh[q], uBhi + off);
                ldsm4(bl[q], uBlo + off);
            }
            #pragma unroll
            for (int mi = 0; mi < 2; mi++)
                #pragma unroll
                for (int nj = 0; nj < 8; nj++) {
                    int q = nj >> 1, hb = (nj & 1) * 2;
                    mma16816(acc[mi][nj], ah[mi], bh[q][hb], bh[q][hb + 1]);
                    mma16816(acc[mi][nj], ah[mi], bl[q][hb], bl[q][hb + 1]);
                    mma16816(acc[mi][nj], al[mi], bh[q][hb], bh[q][hb + 1]);
                }
        }
        __syncthreads();
    }

    #pragma unroll
    for (int mi = 0; mi < 2; mi++) {
        #pragma unroll
        for (int nj = 0; nj < 8; nj++) {
            int r = m0 + wm + mi * 16 + (lane >> 2);
            int cbase = n0 + wn + nj * 8 + (lane & 3) * 2;
            float2 v0, v1;
            v0.x = fmaxf(acc[mi][nj][0], 0.f);
            v0.y = fmaxf(acc[mi][nj][1], 0.f);
            v1.x = fmaxf(acc[mi][nj][2], 0.f);
            v1.y = fmaxf(acc[mi][nj][3], 0.f);
            if (r < N_NODES)
                *(float2*)(out + (size_t)r * DIM + cbase) = v0;
            if (r + 8 < N_NODES)
                *(float2*)(out + (size_t)(r + 8) * DIM + cbase) = v1;
        }
    }
}

// ---------------------------------------------------------------------------
// Launch: prologue on stream 0, then per layer a fork/join two-branch graph:
//   branch A (stream 0):  gather(h0) -> gemm(h0)
//   branch B (stream s2): gather(h1) -> gemm(h1)
// Events/streams are host objects created once; capture records them as
// parallel graph branches (no sync APIs, no allocations).
// ---------------------------------------------------------------------------
extern "C" void kernel_launch(void* const* d_in, const int* in_sizes, int n_in,
                              void* d_out, int out_size) {
    const float* x0   = (const float*)d_in[0];
    const void*  edge = d_in[1];
    const float* W    = (const float*)d_in[2];
    float*       out  = (float*)d_out;

    void *ideg_p, *cursor_p, *bufA_p, *bufB_p;
    cudaGetSymbolAddress(&ideg_p,   g_ideg);
    cudaGetSymbolAddress(&cursor_p, g_cursor);
    cudaGetSymbolAddress(&bufA_p,   g_bufA);
    cudaGetSymbolAddress(&bufB_p,   g_bufB);

    static cudaStream_t s2 = nullptr;
    static cudaEvent_t evF = nullptr, evJ = nullptr;
    if (s2 == nullptr) {
        cudaStreamCreateWithFlags(&s2, cudaStreamNonBlocking);
        cudaEventCreateWithFlags(&evF, cudaEventDisableTiming);
        cudaEventCreateWithFlags(&evJ, cudaEventDisableTiming);
    }

    cudaFuncSetAttribute(gemm_kernel,
                         cudaFuncAttributeMaxDynamicSharedMemorySize,
                         2 * STAGE_BYTES);
    cudaFuncSetAttribute(gemm_kernel,
                         cudaFuncAttributePreferredSharedMemoryCarveout,
                         cudaSharedmemCarveoutMaxShared);

    const int EB = (N_EDGES + 255) / 256;

    // Prologue (layer-invariant), stream 0
    detect_kernel<<<1, 32>>>((const int*)edge);
    cudaMemsetAsync(ideg_p,   0, N_NODES * sizeof(int), 0);
    cudaMemsetAsync(cursor_p, 0, N_NODES * sizeof(int), 0);
    decode_hist_kernel<<<EB, 256>>>(edge);
    scan1_kernel<<<N_SCAN_BLK, SCAN_B>>>();
    scan2_kernel<<<1, 64>>>();
    scan3_kernel<<<N_SCAN_BLK, SCAN_B>>>();
    fill_kernel<<<EB, 256>>>();
    wsplit_kernel<<<(DIM * DIM + 255) / 256, 256>>>(W);

    float* layer_out[5] = {(float*)bufA_p, (float*)bufB_p,
                           (float*)bufA_p, (float*)bufB_p, out};

    const int g0_blocks = H0 * 32 / 256;              // 3136
    const int g1_blocks = (H1 * 32 + 255) / 256;      // 3114
    const dim3 grid_h0(196, 2);
    const dim3 grid_h1(195, 2);

    const float* xin = x0;
    for (int l = 0; l < 5; l++) {
        // Fork: s2 branch depends on everything so far on stream 0
        cudaEventRecord(evF, 0);
        cudaStreamWaitEvent(s2, evF, 0);
        // Branch A (stream 0): half0
        gather_kernel<<<g0_blocks, 256, 0, 0>>>(xin, x0, 0, H0);
        gemm_kernel<<<grid_h0, 256, 2 * STAGE_BYTES, 0>>>(layer_out[l], 0);
        // Branch B (stream s2): half1
        gather_kernel<<<g1_blocks, 256, 0, s2>>>(xin, x0, H0, H1);
        gemm_kernel<<<grid_h1, 256, 2 * STAGE_BYTES, s2>>>(layer_out[l], H0);
        // Join: stream 0 waits for branch B
        cudaEventRecord(evJ, s2);
        cudaStreamWaitEvent(0, evJ, 0);
        xin = layer_out[l];
    }
}